// round 15
// baseline (speedup 1.0000x reference)
#include <cuda_runtime.h>
#include <cuda_fp16.h>
#include <cuda_fp8.h>
#include <cstdint>

// ---------------------------------------------------------------------------
// Problem constants
// ---------------------------------------------------------------------------
#define BBATCH 16
#define TSTEPS 32
#define CCH    512            // hidden channels
#define PPOS   1024           // 32*32 spatial positions
#define OO     2048           // 4 * CCH gate rows
#define NCHUNK 16             // 8 fp16 (term1) + 8 fp8 (corrections)
#define MP     128            // spatial positions per CTA (M)
#define NCHT   16             // channels per CTA

// Correction dequant: both fp8 terms share scale 2^-17
//   term2 = sum (W-w1)*2^15 [w2'] * 4h [h1']      -> * 2^-17
//   term3 = sum 64W [w1']   * (h-h1)*2^11 [h2']   -> * 2^-17
#define S17 7.62939453125e-6f // 2^-17

// ---------------------------------------------------------------------------
// Persistent state (ping-pong h across timesteps)
// g_h16: h1 (fp16, 512/row). g_hf8: [h1'(512) | h2'(512)] e4m3 bytes.
// ---------------------------------------------------------------------------
__device__ __align__(16) __half  g_h16[2][(size_t)BBATCH * PPOS * 512];   // 2 x 16.8 MB
__device__ __align__(16) uint8_t g_hf8[2][(size_t)BBATCH * PPOS * 1024];  // 2 x 16.8 MB
__device__ __align__(16) float   g_cT[(size_t)BBATCH * PPOS * CCH];       // 33 MB
__device__ __align__(16) __half  g_w16[(size_t)OO * 512];                 // w1 fp16
__device__ __align__(16) uint8_t g_wf8[(size_t)OO * 1024];                // [w1'|w2'] e4m3

// ---------------------------------------------------------------------------
// Helpers (compute_80/89-level PTX only)
// ---------------------------------------------------------------------------
__device__ __forceinline__ uint32_t smem_u32(const void* p) {
    uint32_t a;
    asm("{ .reg .u64 t; cvta.to.shared.u64 t, %1; cvt.u32.u64 %0, t; }"
        : "=r"(a) : "l"(p));
    return a;
}

#define SWZ128(o) ((o) ^ (((o) >> 3) & 0x70))

__device__ __forceinline__ void cp_async16(uint32_t dst, const void* src) {
    asm volatile("cp.async.cg.shared.global [%0], [%1], 16;" :: "r"(dst), "l"(src));
}
#define CP_COMMIT()   asm volatile("cp.async.commit_group;" ::: "memory")
#define CP_WAIT(n)    asm volatile("cp.async.wait_group %0;" :: "n"(n) : "memory")

__device__ __forceinline__ void ldsm_x4(uint32_t* r, uint32_t addr) {
    asm volatile("ldmatrix.sync.aligned.m8n8.x4.shared.b16 {%0,%1,%2,%3}, [%4];"
        : "=r"(r[0]), "=r"(r[1]), "=r"(r[2]), "=r"(r[3]) : "r"(addr));
}

// fp16 inputs, f32 accumulate (term 1)
#define MMA_F32(d, a, b) \
    asm volatile( \
        "mma.sync.aligned.m16n8k16.row.col.f32.f16.f16.f32 " \
        "{%0,%1,%2,%3}, {%4,%5,%6,%7}, {%8,%9}, {%0,%1,%2,%3};" \
        : "+f"((d)[0]), "+f"((d)[1]), "+f"((d)[2]), "+f"((d)[3]) \
        : "r"((a)[0]), "r"((a)[1]), "r"((a)[2]), "r"((a)[3]), \
          "r"((b)[0]), "r"((b)[1]))

// e4m3 inputs, f32 accumulate, k32 (corrections) — 2x MAC per instruction
#define MMA_FP8(d, a, b) \
    asm volatile( \
        "mma.sync.aligned.m16n8k32.row.col.f32.e4m3.e4m3.f32 " \
        "{%0,%1,%2,%3}, {%4,%5,%6,%7}, {%8,%9}, {%0,%1,%2,%3};" \
        : "+f"((d)[0]), "+f"((d)[1]), "+f"((d)[2]), "+f"((d)[3]) \
        : "r"((a)[0]), "r"((a)[1]), "r"((a)[2]), "r"((a)[3]), \
          "r"((b)[0]), "r"((b)[1]))

__device__ __forceinline__ float sigf(float v) { return 1.0f / (1.0f + __expf(-v)); }
__device__ __forceinline__ float tanh_f(float v) { return 2.0f * sigf(2.0f * v) - 1.0f; }

__device__ __forceinline__ float fp8_to_f(uint8_t b) {
    return float(*reinterpret_cast<const __nv_fp8_e4m3*>(&b));
}
__device__ __forceinline__ uint8_t f_to_fp8(float v) {
    __nv_fp8_e4m3 t(v);
    return *reinterpret_cast<const uint8_t*>(&t);
}

// ---------------------------------------------------------------------------
// Init kernels
// ---------------------------------------------------------------------------
__global__ void init_state_kernel() {
    const size_t NH16 = (size_t)BBATCH * PPOS * 512 / 2;   // h16 buf0 u32 words
    const size_t NH8  = (size_t)BBATCH * PPOS * 1024 / 4;  // hf8 buf0 u32 words
    const size_t NC   = (size_t)BBATCH * PPOS * CCH;
    size_t i = (size_t)blockIdx.x * 256 + threadIdx.x;
    if (i < NH16) ((uint32_t*)g_h16[0])[i] = 0u;
    if (i < NH8)  ((uint32_t*)g_hf8[0])[i] = 0u;
    if (i < NC)   g_cT[i] = 0.0f;
}

// w1 = fp16(W); w1' = e4m3(64 W); w2' = e4m3((W - w1) * 2^15)
__global__ void build_w_kernel(const float* __restrict__ W) {
    int i = blockIdx.x * 256 + threadIdx.x;
    if (i >= OO * CCH) return;
    int o = i >> 9, c = i & 511;
    float w  = W[(size_t)o * 513 + 1 + c];
    __half w1 = __float2half_rn(w);
    float r   = w - __half2float(w1);
    g_w16[(size_t)o * 512 + c]        = w1;
    g_wf8[(size_t)o * 1024 + c]       = f_to_fp8(w * 64.0f);
    g_wf8[(size_t)o * 1024 + 512 + c] = f_to_fp8(r * 32768.0f);
}

// ---------------------------------------------------------------------------
// Fused kernel: mixed fp16/fp8 gates-GEMM + LSTM for step t (blockIdx.y < 32)
// and, overlapped, the 3x3 post-conv for step t-1 (blockIdx.y in [32,36)).
// Both only READ h buffers [t&1]; GEMM writes [(t+1)&1] -> no race.
//
// GEMM: 128 thr = 4 warps (2m x 2n), warp tile 64x32, CTA 128(p) x 64
// (n = 2 warps x [4 gates x 8 ch] interleaved). 16 chunks of 128B rows:
//   c 0-7 : fp16 w1*h1, k64/chunk  -> acc1 (f32)      [MMA_F32, k16 x4]
//   c 8-11: fp8  w2'*h1', k128/chunk -> acc2 (f32)    [MMA_FP8, k32 x4]
//   c12-15: fp8  w1'*h2', k128/chunk -> acc2 (shared scale 2^-17)
// Identical swizzled addressing for all chunks (validated in R12/R14).
// ---------------------------------------------------------------------------
#define STAGE_SZ   24576                  // A 16KB + B 8KB
#define SM_A(s)    ((s) * STAGE_SZ)
#define SM_B(s)    ((s) * STAGE_SZ + 16384)
#define SM_W0      73728                  // 64 floats
#define SM_BIAS    74240                  // 64 floats
#define SM_X       74752                  // 128 floats
#define SMEM_TOTAL (75264 + 1024)         // + align slack (~76 KB -> 2 CTAs/SM)

__global__ __launch_bounds__(128, 2) void fused_step_kernel(
    const float* __restrict__ W,      // [2048][513]
    const float* __restrict__ bconv,  // [2048]
    const float* __restrict__ x,      // [B][T][1024]
    const float* __restrict__ Wp,     // [512][3][3]
    const float* __restrict__ bpost,  // [1]
    float* __restrict__ out,          // [B][T][1024]
    int t)
{
    extern __shared__ char smem_raw[];
    const int tid = threadIdx.x;

    // =========================== CONV BRANCH ===============================
    if (blockIdx.y >= 32) {
        if (t == 0) return;
        float* sWp = (float*)smem_raw;
        for (int i = tid; i < 512 * 9; i += 128) sWp[i] = Wp[i];
        __syncthreads();

        const int b    = blockIdx.z;
        const int wid  = tid >> 5;
        const int lane = tid & 31;
        const int wg   = ((blockIdx.y - 32) * 8 + blockIdx.x) * 4 + wid;  // 0..127
        const __half*  __restrict__ hb1 = g_h16[t & 1] + (size_t)b * PPOS * 512;
        const uint8_t* __restrict__ hb8 = g_hf8[t & 1] + (size_t)b * PPOS * 1024;

#pragma unroll 1
        for (int pp = 0; pp < 8; pp++) {
            const int pix = wg * 8 + pp;
            const int py = pix >> 5, px = pix & 31;
            float acc = 0.0f;
#pragma unroll
            for (int dy = -1; dy <= 1; dy++) {
                int yy = py + dy;
                if (yy < 0 || yy > 31) continue;
#pragma unroll
                for (int dx = -1; dx <= 1; dx++) {
                    int xx = px + dx;
                    if (xx < 0 || xx > 31) continue;
                    const __half*  hr1 = hb1 + (size_t)(yy * 32 + xx) * 512;
                    const uint8_t* hr8 = hb8 + (size_t)(yy * 32 + xx) * 1024 + 512;
                    int e = (dy + 1) * 3 + (dx + 1);
#pragma unroll
                    for (int j = 0; j < 8; j++) {
                        int cc = j * 64 + 2 * lane;
                        __half2 d1 = *(const __half2*)(hr1 + cc);
                        float h0 = __half2float(d1.x) + fp8_to_f(hr8[cc])     * 4.8828125e-4f;
                        float h1 = __half2float(d1.y) + fp8_to_f(hr8[cc + 1]) * 4.8828125e-4f;
                        acc += h0 * sWp[cc * 9 + e] + h1 * sWp[(cc + 1) * 9 + e];
                    }
                }
            }
#pragma unroll
            for (int off = 16; off > 0; off >>= 1)
                acc += __shfl_xor_sync(0xFFFFFFFFu, acc, off);
            if (lane == 0)
                out[((size_t)b * TSTEPS + (t - 1)) * PPOS + pix] = acc + bpost[0];
        }
        return;
    }

    // =========================== GEMM BRANCH ===============================
    const uint32_t sbase0 = smem_u32(smem_raw);
    const uint32_t abase  = (sbase0 + 1023) & ~1023u;
    char* smem = smem_raw + (abase - sbase0);

    const int wid  = tid >> 5;
    const int lane = tid & 31;
    const int mw   = wid >> 1;          // 0..1  (m warp)
    const int nw   = wid & 1;           // 0..1  (n warp: 8-ch group)

    const int b   = blockIdx.z;
    const int ch0 = blockIdx.y * NCHT;  // 16 channels per CTA
    const int p0  = blockIdx.x * MP;

    const __half*  __restrict__ hb1 = g_h16[t & 1] + (size_t)b * PPOS * 512;
    const uint8_t* __restrict__ hb8 = g_hf8[t & 1] + (size_t)b * PPOS * 1024;
    __half*  __restrict__ hwr1 = g_h16[(t + 1) & 1];
    uint8_t* __restrict__ hwr8 = g_hf8[(t + 1) & 1];

    // stage loader: chunk c -> stage s.  A: 1024 x 16B, B: 512 x 16B rows of 128B.
    //   c<8   : A = h1 fp16 (row 1024B) at c*128B;   B = w1 fp16 at c*128B
    //   8-11  : A = h1' fp8 at (c-8)*128;            B = w2' fp8 at 512+(c-8)*128
    //   12-15 : A = h2' fp8 at 512+(c-12)*128;       B = w1' fp8 at (c-12)*128
    // B row r (0..63): o = gate*512 + ch0 + (r>>5)*8 + (r&7), gate = (r>>3)&3.
    auto load_stage = [&](int c, int s) {
        const uint32_t da = abase + SM_A(s);
        const uint32_t db = abase + SM_B(s);
        if (c < 8) {
            const int ka = c * 64;                          // halfs
#pragma unroll
            for (int i = 0; i < 8; i++) {
                int idx = tid + i * 128;
                int r = idx >> 3, c8 = idx & 7;
                cp_async16(da + SWZ128(r * 128 + c8 * 16),
                           hb1 + (size_t)(p0 + r) * 512 + ka + c8 * 8);
            }
#pragma unroll
            for (int i = 0; i < 4; i++) {
                int idx = tid + i * 128;
                int r = idx >> 3, c8 = idx & 7;
                int o = (((r >> 3) & 3) * 512) + ch0 + ((r >> 5) * 8) + (r & 7);
                cp_async16(db + SWZ128(r * 128 + c8 * 16),
                           g_w16 + (size_t)o * 512 + ka + c8 * 8);
            }
        } else {
            const int ha = (c < 12) ? ((c - 8) * 128) : (512 + (c - 12) * 128);
            const int wa = (c < 12) ? (512 + (c - 8) * 128) : ((c - 12) * 128);
#pragma unroll
            for (int i = 0; i < 8; i++) {
                int idx = tid + i * 128;
                int r = idx >> 3, c8 = idx & 7;
                cp_async16(da + SWZ128(r * 128 + c8 * 16),
                           hb8 + (size_t)(p0 + r) * 1024 + ha + c8 * 16);
            }
#pragma unroll
            for (int i = 0; i < 4; i++) {
                int idx = tid + i * 128;
                int r = idx >> 3, c8 = idx & 7;
                int o = (((r >> 3) & 3) * 512) + ch0 + ((r >> 5) * 8) + (r & 7);
                cp_async16(db + SWZ128(r * 128 + c8 * 16),
                           g_wf8 + (size_t)o * 1024 + wa + c8 * 16);
            }
        }
        CP_COMMIT();
    };

    load_stage(0, 0);
    load_stage(1, 1);
    {
        float* sW0   = (float*)(smem + SM_W0);
        float* sBias = (float*)(smem + SM_BIAS);
        float* sX    = (float*)(smem + SM_X);
        if (tid < 64) {                            // idx = g*16 + c16
            int o = (tid >> 4) * 512 + ch0 + (tid & 15);
            sW0[tid]   = W[(size_t)o * 513];
            sBias[tid] = bconv[o];
        }
        sX[tid] = x[((size_t)b * TSTEPS + t) * PPOS + p0 + tid];
    }

    float acc1[4][4][4];                           // term1 (64 regs)
    float acc2[4][4][4];                           // fp8 corrections (64 regs)
#pragma unroll
    for (int mt = 0; mt < 4; mt++)
#pragma unroll
        for (int nt = 0; nt < 4; nt++)
#pragma unroll
            for (int e = 0; e < 4; e++) { acc1[mt][nt][e] = 0.0f; acc2[mt][nt][e] = 0.0f; }

    // Base swizzled ldmatrix addresses (kk=0); +16-row steps (+2048B) keep the
    // SW128 mask; kk steps are pure XOR with kk*32 (mask depends on row&7 only).
    const uint32_t rA0 = SWZ128((uint32_t)(mw * 64 + (lane & 15)) * 128
                                + (uint32_t)(lane >> 4) * 16);
    const uint32_t rB0 = SWZ128((uint32_t)((lane & 7) + ((lane >> 4) << 3)) * 128
                                + (uint32_t)((lane >> 3) & 1) * 16);
    const uint32_t nwofs = (uint32_t)nw * 32 * 128;   // n-warp row offset (mask-safe)

#pragma unroll 1
    for (int c = 0; c < NCHUNK; c++) {
        const int s = c % 3;
        if (c + 2 < NCHUNK) CP_WAIT(1); else CP_WAIT(0);
        __syncthreads();                           // chunk c ready; stage (c+2)%3 free
        if (c + 2 < NCHUNK) load_stage(c + 2, (c + 2) % 3);

        const uint32_t Ab = abase + SM_A(s);
        const uint32_t Bb = abase + SM_B(s);
        if (c < 8) {
#pragma unroll
            for (int kk = 0; kk < 4; kk++) {
                uint32_t af[4][4], bf[2][4];
#pragma unroll
                for (int mt = 0; mt < 4; mt++)
                    ldsm_x4(af[mt], Ab + ((rA0 + mt * 2048) ^ (kk * 32)));
#pragma unroll
                for (int np = 0; np < 2; np++)
                    ldsm_x4(bf[np], Bb + nwofs + ((rB0 + np * 2048) ^ (kk * 32)));
#pragma unroll
                for (int mt = 0; mt < 4; mt++)
#pragma unroll
                    for (int nt = 0; nt < 4; nt++)
                        MMA_F32(acc1[mt][nt], af[mt], &bf[nt >> 1][(nt & 1) * 2]);
            }
        } else {
#pragma unroll
            for (int kk = 0; kk < 4; kk++) {
                uint32_t af[4][4], bf[2][4];
#pragma unroll
                for (int mt = 0; mt < 4; mt++)
                    ldsm_x4(af[mt], Ab + ((rA0 + mt * 2048) ^ (kk * 32)));
#pragma unroll
                for (int np = 0; np < 2; np++)
                    ldsm_x4(bf[np], Bb + nwofs + ((rB0 + np * 2048) ^ (kk * 32)));
#pragma unroll
                for (int mt = 0; mt < 4; mt++)
#pragma unroll
                    for (int nt = 0; nt < 4; nt++)
                        MMA_FP8(acc2[mt][nt], af[mt], &bf[nt >> 1][(nt & 1) * 2]);
            }
        }
    }

    // ---- register-resident dequant + LSTM epilogue ----
    float* sW0   = (float*)(smem + SM_W0);
    float* sBias = (float*)(smem + SM_BIAS);
    float* sX    = (float*)(smem + SM_X);

#pragma unroll
    for (int mt = 0; mt < 4; mt++) {
#pragma unroll
        for (int half = 0; half < 2; half++) {
            const int m = mw * 64 + mt * 16 + (lane >> 2) + half * 8;
            const int p = p0 + m;
            const float xv = sX[m];
            float* __restrict__ cb = g_cT + ((size_t)b * PPOS + p) * CCH;
            __half*  __restrict__ hr1 = hwr1 + ((size_t)b * PPOS + p) * 512;
            uint8_t* __restrict__ hr8 = hwr8 + ((size_t)b * PPOS + p) * 1024;
            const int chb = ch0 + nw * 8 + (lane & 3) * 2;
            float2 cold = *(float2*)(cb + chb);
            float cn[2];
            __half2 d1o;
            uint8_t b1o[2], b2o[2];
#pragma unroll
            for (int e = 0; e < 2; e++) {
                const int idx = half * 2 + e;
                const int cfs = nw * 8 + (lane & 3) * 2 + e;   // 0..15
                float g4[4];
#pragma unroll
                for (int g = 0; g < 4; g++) {
                    g4[g] = acc1[mt][g][idx] + acc2[mt][g][idx] * S17
                          + sW0[g * 16 + cfs] * xv + sBias[g * 16 + cfs];
                }
                float cold_e = (e == 0) ? cold.x : cold.y;
                cn[e] = sigf(g4[1]) * cold_e + sigf(g4[0]) + tanh_f(g4[3]);
                float hv = sigf(g4[2]) + tanh_f(cn[e]);
                __half h1 = __float2half_rn(hv);
                if (e == 0) d1o.x = h1; else d1o.y = h1;
                b1o[e] = f_to_fp8(hv * 4.0f);
                b2o[e] = f_to_fp8((hv - __half2float(h1)) * 2048.0f);
            }
            *(float2*)(cb + chb) = make_float2(cn[0], cn[1]);
            *(__half2*)(hr1 + chb) = d1o;
            hr8[chb]           = b1o[0];
            hr8[chb + 1]       = b1o[1];
            hr8[512 + chb]     = b2o[0];
            hr8[512 + chb + 1] = b2o[1];
        }
    }
}

// ---------------------------------------------------------------------------
// Standalone post-conv (only for the final step t=31).
// ---------------------------------------------------------------------------
__global__ __launch_bounds__(256) void post_conv_kernel(
    const float* __restrict__ Wp,
    const float* __restrict__ bpost,
    float* __restrict__ out,
    int t)
{
    __shared__ float sWp[512 * 9];
    for (int i = threadIdx.x; i < 512 * 9; i += 256) sWp[i] = Wp[i];
    __syncthreads();

    int warp = (blockIdx.x * 256 + threadIdx.x) >> 5;
    int lane = threadIdx.x & 31;
    int b  = warp >> 10;
    int py = (warp >> 5) & 31;
    int px = warp & 31;

    const __half*  __restrict__ hb1 = g_h16[(t + 1) & 1] + (size_t)b * PPOS * 512;
    const uint8_t* __restrict__ hb8 = g_hf8[(t + 1) & 1] + (size_t)b * PPOS * 1024;
    float acc = 0.0f;

#pragma unroll
    for (int dy = -1; dy <= 1; dy++) {
        int yy = py + dy;
        if (yy < 0 || yy > 31) continue;
#pragma unroll
        for (int dx = -1; dx <= 1; dx++) {
            int xx = px + dx;
            if (xx < 0 || xx > 31) continue;
            const __half*  hr1 = hb1 + (size_t)(yy * 32 + xx) * 512;
            const uint8_t* hr8 = hb8 + (size_t)(yy * 32 + xx) * 1024 + 512;
            int e = (dy + 1) * 3 + (dx + 1);
#pragma unroll
            for (int j = 0; j < 8; j++) {
                int cc = j * 64 + 2 * lane;
                __half2 d1 = *(const __half2*)(hr1 + cc);
                float h0 = __half2float(d1.x) + fp8_to_f(hr8[cc])     * 4.8828125e-4f;
                float h1 = __half2float(d1.y) + fp8_to_f(hr8[cc + 1]) * 4.8828125e-4f;
                acc += h0 * sWp[cc * 9 + e] + h1 * sWp[(cc + 1) * 9 + e];
            }
        }
    }

#pragma unroll
    for (int off = 16; off > 0; off >>= 1)
        acc += __shfl_xor_sync(0xFFFFFFFFu, acc, off);
    if (lane == 0)
        out[((size_t)b * TSTEPS + t) * PPOS + py * 32 + px] = acc + bpost[0];
}

// ---------------------------------------------------------------------------
extern "C" void kernel_launch(void* const* d_in, const int* in_sizes, int n_in,
                              void* d_out, int out_size)
{
    const float* x      = (const float*)d_in[0];
    const float* W_conv = (const float*)d_in[1];
    const float* b_conv = (const float*)d_in[2];
    const float* W_post = (const float*)d_in[3];
    const float* b_post = (const float*)d_in[4];
    float* out = (float*)d_out;

    static bool attr_set = false;
    if (!attr_set) {
        cudaFuncSetAttribute(fused_step_kernel,
                             cudaFuncAttributeMaxDynamicSharedMemorySize, SMEM_TOTAL);
        attr_set = true;
    }

    {
        size_t n = (size_t)BBATCH * PPOS * CCH;        // >= all word counts
        init_state_kernel<<<(unsigned)((n + 255) / 256), 256>>>();
    }
    build_w_kernel<<<(OO * CCH + 255) / 256, 256>>>(W_conv);

    dim3 fgrid(8, 36, BBATCH);   // y<32: gemm tiles (16ch each), y in [32,36): conv
    for (int t = 0; t < TSTEPS; t++) {
        fused_step_kernel<<<fgrid, 128, SMEM_TOTAL>>>(W_conv, b_conv, x,
                                                      W_post, b_post, out, t);
    }
    post_conv_kernel<<<2048, 256>>>(W_post, b_post, out, 31);
}

// round 16
// speedup vs baseline: 1.3535x; 1.3535x over previous
#include <cuda_runtime.h>
#include <cuda_fp16.h>
#include <cstdint>

// ---------------------------------------------------------------------------
// Problem constants
// ---------------------------------------------------------------------------
#define BBATCH 16
#define TSTEPS 32
#define CCH    512            // hidden channels
#define PPOS   1024           // 32*32 spatial positions
#define OO     2048           // 4 * CCH gate rows
#define KQ     1024           // stored h width: [h1(512) | h2(512)] fp16
#define NCHUNK 16             // 8 chunks w1*h1 (f32 acc) + 8 chunks w1*h2 (f16 acc)
#define MP     128            // spatial positions per CTA (M)
#define NCHT   16             // channels per CTA

// h = h1 + h2 * 2^-10  (w2*h1 term dropped: ~1.4e-4/step, margin-checked)
#define S3 9.765625e-4f       // 2^-10

// ---------------------------------------------------------------------------
// Persistent state (ping-pong h digits across timesteps)
// ---------------------------------------------------------------------------
__device__ __align__(16) __half g_h16[2][(size_t)BBATCH * PPOS * KQ];  // 2 x 33.5 MB
__device__ __align__(16) float  g_cT[(size_t)BBATCH * PPOS * CCH];     // 33 MB
__device__ __align__(16) __half g_w16[(size_t)OO * 512];               // w1 only, 2.1 MB

// ---------------------------------------------------------------------------
// Helpers (compute_80-level PTX only)
// ---------------------------------------------------------------------------
__device__ __forceinline__ uint32_t smem_u32(const void* p) {
    uint32_t a;
    asm("{ .reg .u64 t; cvta.to.shared.u64 t, %1; cvt.u32.u64 %0, t; }"
        : "=r"(a) : "l"(p));
    return a;
}

#define SWZ128(o) ((o) ^ (((o) >> 3) & 0x70))

__device__ __forceinline__ void cp_async16(uint32_t dst, const void* src) {
    asm volatile("cp.async.cg.shared.global [%0], [%1], 16;" :: "r"(dst), "l"(src));
}
#define CP_COMMIT()   asm volatile("cp.async.commit_group;" ::: "memory")
#define CP_WAIT(n)    asm volatile("cp.async.wait_group %0;" :: "n"(n) : "memory")

__device__ __forceinline__ void ldsm_x4(uint32_t* r, uint32_t addr) {
    asm volatile("ldmatrix.sync.aligned.m8n8.x4.shared.b16 {%0,%1,%2,%3}, [%4];"
        : "=r"(r[0]), "=r"(r[1]), "=r"(r[2]), "=r"(r[3]) : "r"(addr));
}

// fp16 inputs, f32 accumulate (term 1)
#define MMA_F32(d, a, b) \
    asm volatile( \
        "mma.sync.aligned.m16n8k16.row.col.f32.f16.f16.f32 " \
        "{%0,%1,%2,%3}, {%4,%5,%6,%7}, {%8,%9}, {%0,%1,%2,%3};" \
        : "+f"((d)[0]), "+f"((d)[1]), "+f"((d)[2]), "+f"((d)[3]) \
        : "r"((a)[0]), "r"((a)[1]), "r"((a)[2]), "r"((a)[3]), \
          "r"((b)[0]), "r"((b)[1]))

// fp16 inputs, f16 accumulate (term 2)
#define MMA_F16(d, a, b) \
    asm volatile( \
        "mma.sync.aligned.m16n8k16.row.col.f16.f16.f16.f16 " \
        "{%0,%1}, {%2,%3,%4,%5}, {%6,%7}, {%0,%1};" \
        : "+r"((d)[0]), "+r"((d)[1]) \
        : "r"((a)[0]), "r"((a)[1]), "r"((a)[2]), "r"((a)[3]), \
          "r"((b)[0]), "r"((b)[1]))

__device__ __forceinline__ float sigf(float v) { return 1.0f / (1.0f + __expf(-v)); }
__device__ __forceinline__ float tanh_f(float v) { return 2.0f * sigf(2.0f * v) - 1.0f; }

// ---------------------------------------------------------------------------
// Init kernels
// ---------------------------------------------------------------------------
__global__ void init_state_kernel() {
    const size_t NH = (size_t)BBATCH * PPOS * KQ / 2;     // buf0 as u32 words
    const size_t NC = (size_t)BBATCH * PPOS * CCH;
    size_t i = (size_t)blockIdx.x * 256 + threadIdx.x;
    if (i < NH) ((uint32_t*)g_h16[0])[i] = 0u;
    if (i < NC) g_cT[i] = 0.0f;
}

// w1 = fp16(W[:,1:513])
__global__ void build_w16_kernel(const float* __restrict__ W) {
    int i = blockIdx.x * 256 + threadIdx.x;
    if (i >= OO * CCH) return;
    int o = i >> 9, c = i & 511;
    g_w16[(size_t)o * 512 + c] = __float2half_rn(W[(size_t)o * 513 + 1 + c]);
}

// ---------------------------------------------------------------------------
// Fused kernel: 2-term split-fp16 gates-GEMM + LSTM for step t (blockIdx.y<32)
// and, overlapped, the 3x3 post-conv for step t-1 (blockIdx.y in [32,36)).
// Both only READ h buffer [t&1]; the GEMM writes [(t+1)&1] -> no race.
//
// GEMM: 128 thr = 4 warps (2m x 2n), warp tile 64x32, CTA tile 128(p) x 64
// (n = 2 warps x [4 gates x 8 ch] interleaved, nt == gate). 16 chunks of 64
// fp16: c 0-7 w1*h1 -> f32 acc; c 8-15 w1*h2 -> f16 acc (dequant 2^-10).
// B tile identical for both terms (w1). Register-resident LSTM epilogue.
// ---------------------------------------------------------------------------
#define STAGE_SZ   24576                  // A 16KB + B 8KB
#define SM_A(s)    ((s) * STAGE_SZ)
#define SM_B(s)    ((s) * STAGE_SZ + 16384)
#define SM_W0      73728                  // 64 floats
#define SM_BIAS    74240                  // 64 floats
#define SM_X       74752                  // 128 floats
#define SMEM_TOTAL (75264 + 1024)         // + align slack (~76 KB -> 2 CTAs/SM)

__global__ __launch_bounds__(128, 2) void fused_step_kernel(
    const float* __restrict__ W,      // [2048][513]
    const float* __restrict__ bconv,  // [2048]
    const float* __restrict__ x,      // [B][T][1024]
    const float* __restrict__ Wp,     // [512][3][3]
    const float* __restrict__ bpost,  // [1]
    float* __restrict__ out,          // [B][T][1024]
    int t)
{
    extern __shared__ char smem_raw[];
    const int tid = threadIdx.x;

    // =========================== CONV BRANCH ===============================
    if (blockIdx.y >= 32) {
        if (t == 0) return;
        float* sWp = (float*)smem_raw;
        for (int i = tid; i < 512 * 9; i += 128) sWp[i] = Wp[i];
        __syncthreads();

        const int b    = blockIdx.z;
        const int wid  = tid >> 5;
        const int lane = tid & 31;
        const int wg   = ((blockIdx.y - 32) * 8 + blockIdx.x) * 4 + wid;  // 0..127
        const __half* __restrict__ hb = g_h16[t & 1] + (size_t)b * PPOS * KQ;

#pragma unroll 1
        for (int pp = 0; pp < 8; pp++) {
            const int pix = wg * 8 + pp;
            const int py = pix >> 5, px = pix & 31;
            float acc = 0.0f;
#pragma unroll
            for (int dy = -1; dy <= 1; dy++) {
                int yy = py + dy;
                if (yy < 0 || yy > 31) continue;
#pragma unroll
                for (int dx = -1; dx <= 1; dx++) {
                    int xx = px + dx;
                    if (xx < 0 || xx > 31) continue;
                    const __half* hr = hb + (size_t)(yy * 32 + xx) * KQ;
                    int e = (dy + 1) * 3 + (dx + 1);
#pragma unroll
                    for (int j = 0; j < 8; j++) {
                        int cc = j * 64 + 2 * lane;
                        __half2 d1 = *(const __half2*)(hr + cc);
                        __half2 d2 = *(const __half2*)(hr + 512 + cc);
                        float h0 = __half2float(d1.x) + __half2float(d2.x) * S3;
                        float h1 = __half2float(d1.y) + __half2float(d2.y) * S3;
                        acc += h0 * sWp[cc * 9 + e] + h1 * sWp[(cc + 1) * 9 + e];
                    }
                }
            }
#pragma unroll
            for (int off = 16; off > 0; off >>= 1)
                acc += __shfl_xor_sync(0xFFFFFFFFu, acc, off);
            if (lane == 0)
                out[((size_t)b * TSTEPS + (t - 1)) * PPOS + pix] = acc + bpost[0];
        }
        return;
    }

    // =========================== GEMM BRANCH ===============================
    const uint32_t sbase0 = smem_u32(smem_raw);
    const uint32_t abase  = (sbase0 + 1023) & ~1023u;
    char* smem = smem_raw + (abase - sbase0);

    const int wid  = tid >> 5;
    const int lane = tid & 31;
    const int mw   = wid >> 1;          // 0..1  (m warp)
    const int nw   = wid & 1;           // 0..1  (n warp: 8-ch group)

    const int b   = blockIdx.z;
    const int ch0 = blockIdx.y * NCHT;  // 16 channels per CTA
    const int p0  = blockIdx.x * MP;

    const __half* __restrict__ hb = g_h16[t & 1] + (size_t)b * PPOS * KQ;
    __half* __restrict__ hwr      = g_h16[(t + 1) & 1];

    // stage loader: chunk c -> stage s.  A: 1024 x 16B, B: 512 x 16B.
    // A digit: c<8 -> h1, else h2; k-offset (c&7)*64. B always w1 at (c&7)*64.
    // B row r (0..63): o = gate*512 + ch0 + (r>>5)*8 + (r&7), gate = (r>>3)&3.
    auto load_stage = [&](int c, int s) {
        const int ha = ((c < 8) ? 0 : 512) + (c & 7) * 64;
        const int wa = (c & 7) * 64;
        const uint32_t da = abase + SM_A(s);
#pragma unroll
        for (int i = 0; i < 8; i++) {
            int idx = tid + i * 128;
            int r = idx >> 3, c8 = idx & 7;
            cp_async16(da + SWZ128(r * 128 + c8 * 16),
                       hb + (size_t)(p0 + r) * KQ + ha + c8 * 8);
        }
        const uint32_t db = abase + SM_B(s);
#pragma unroll
        for (int i = 0; i < 4; i++) {
            int idx = tid + i * 128;
            int r = idx >> 3, c8 = idx & 7;
            int o = (((r >> 3) & 3) * 512) + ch0 + ((r >> 5) * 8) + (r & 7);
            cp_async16(db + SWZ128(r * 128 + c8 * 16),
                       g_w16 + (size_t)o * 512 + wa + c8 * 8);
        }
        CP_COMMIT();
    };

    load_stage(0, 0);
    load_stage(1, 1);
    {
        float* sW0   = (float*)(smem + SM_W0);
        float* sBias = (float*)(smem + SM_BIAS);
        float* sX    = (float*)(smem + SM_X);
        if (tid < 64) {                            // idx = g*16 + c16
            int o = (tid >> 4) * 512 + ch0 + (tid & 15);
            sW0[tid]   = W[(size_t)o * 513];
            sBias[tid] = bconv[o];
        }
        sX[tid] = x[((size_t)b * TSTEPS + t) * PPOS + p0 + tid];
    }

    float    acc1[4][4][4];                        // term1, f32 acc (64 regs)
    uint32_t acc2[4][4][2];                        // term2, f16x2 acc (32 regs)
#pragma unroll
    for (int mt = 0; mt < 4; mt++)
#pragma unroll
        for (int nt = 0; nt < 4; nt++) {
#pragma unroll
            for (int e = 0; e < 4; e++) acc1[mt][nt][e] = 0.0f;
            acc2[mt][nt][0] = 0u; acc2[mt][nt][1] = 0u;
        }

    // Base swizzled ldmatrix addresses (kk=0); +16-row steps (+2048B) keep the
    // SW128 mask; kk steps are pure XOR with kk*32 (mask depends on row&7 only).
    const uint32_t rA0 = SWZ128((uint32_t)(mw * 64 + (lane & 15)) * 128
                                + (uint32_t)(lane >> 4) * 16);
    const uint32_t rB0 = SWZ128((uint32_t)((lane & 7) + ((lane >> 4) << 3)) * 128
                                + (uint32_t)((lane >> 3) & 1) * 16);
    const uint32_t nwofs = (uint32_t)nw * 32 * 128;   // n-warp row offset (mask-safe)

#pragma unroll 1
    for (int c = 0; c < NCHUNK; c++) {
        const int s = c % 3;
        if (c + 2 < NCHUNK) CP_WAIT(1); else CP_WAIT(0);
        __syncthreads();                           // chunk c ready; stage (c+2)%3 free
        if (c + 2 < NCHUNK) load_stage(c + 2, (c + 2) % 3);

        const uint32_t Ab = abase + SM_A(s);
        const uint32_t Bb = abase + SM_B(s);
        if (c < 8) {
#pragma unroll
            for (int kk = 0; kk < 4; kk++) {
                uint32_t af[4][4], bf[2][4];
#pragma unroll
                for (int mt = 0; mt < 4; mt++)
                    ldsm_x4(af[mt], Ab + ((rA0 + mt * 2048) ^ (kk * 32)));
#pragma unroll
                for (int np = 0; np < 2; np++)
                    ldsm_x4(bf[np], Bb + nwofs + ((rB0 + np * 2048) ^ (kk * 32)));
#pragma unroll
                for (int mt = 0; mt < 4; mt++)
#pragma unroll
                    for (int nt = 0; nt < 4; nt++)
                        MMA_F32(acc1[mt][nt], af[mt], &bf[nt >> 1][(nt & 1) * 2]);
            }
        } else {
#pragma unroll
            for (int kk = 0; kk < 4; kk++) {
                uint32_t af[4][4], bf[2][4];
#pragma unroll
                for (int mt = 0; mt < 4; mt++)
                    ldsm_x4(af[mt], Ab + ((rA0 + mt * 2048) ^ (kk * 32)));
#pragma unroll
                for (int np = 0; np < 2; np++)
                    ldsm_x4(bf[np], Bb + nwofs + ((rB0 + np * 2048) ^ (kk * 32)));
#pragma unroll
                for (int mt = 0; mt < 4; mt++)
#pragma unroll
                    for (int nt = 0; nt < 4; nt++)
                        MMA_F16(acc2[mt][nt], af[mt], &bf[nt >> 1][(nt & 1) * 2]);
            }
        }
    }

    // ---- register-resident dequant + LSTM epilogue ----
    float* sW0   = (float*)(smem + SM_W0);
    float* sBias = (float*)(smem + SM_BIAS);
    float* sX    = (float*)(smem + SM_X);

#pragma unroll
    for (int mt = 0; mt < 4; mt++) {
#pragma unroll
        for (int half = 0; half < 2; half++) {
            const int m = mw * 64 + mt * 16 + (lane >> 2) + half * 8;
            const int p = p0 + m;
            const float xv = sX[m];
            float* __restrict__ cb = g_cT + ((size_t)b * PPOS + p) * CCH;
            __half* __restrict__ hr = hwr + ((size_t)b * PPOS + p) * KQ;
            const int chb = ch0 + nw * 8 + (lane & 3) * 2;
            float2 cold = *(float2*)(cb + chb);
            float cn[2];
            __half2 d1o, d2o;
#pragma unroll
            for (int e = 0; e < 2; e++) {
                const int idx = half * 2 + e;
                const int cfs = nw * 8 + (lane & 3) * 2 + e;   // 0..15
                float g4[4];
#pragma unroll
                for (int g = 0; g < 4; g++) {
                    __half2 t3 = *(__half2*)&acc2[mt][g][half];
                    float v3 = (e == 0) ? __half2float(t3.x) : __half2float(t3.y);
                    g4[g] = acc1[mt][g][idx] + v3 * S3
                          + sW0[g * 16 + cfs] * xv + sBias[g * 16 + cfs];
                }
                float cold_e = (e == 0) ? cold.x : cold.y;
                cn[e] = sigf(g4[1]) * cold_e + sigf(g4[0]) + tanh_f(g4[3]);
                float hv = sigf(g4[2]) + tanh_f(cn[e]);
                __half h1 = __float2half_rn(hv);
                __half h2 = __float2half_rn((hv - __half2float(h1)) * 1024.0f);
                if (e == 0) { d1o.x = h1; d2o.x = h2; }
                else        { d1o.y = h1; d2o.y = h2; }
            }
            *(float2*)(cb + chb) = make_float2(cn[0], cn[1]);
            *(__half2*)(hr + chb)       = d1o;
            *(__half2*)(hr + 512 + chb) = d2o;
        }
    }
}

// ---------------------------------------------------------------------------
// Standalone post-conv (only for the final step t=31), fp16 h digits.
// ---------------------------------------------------------------------------
__global__ __launch_bounds__(256) void post_conv_kernel(
    const float* __restrict__ Wp,
    const float* __restrict__ bpost,
    float* __restrict__ out,
    int t)
{
    __shared__ float sWp[512 * 9];
    for (int i = threadIdx.x; i < 512 * 9; i += 256) sWp[i] = Wp[i];
    __syncthreads();

    int warp = (blockIdx.x * 256 + threadIdx.x) >> 5;
    int lane = threadIdx.x & 31;
    int b  = warp >> 10;
    int py = (warp >> 5) & 31;
    int px = warp & 31;

    const __half* __restrict__ hb = g_h16[(t + 1) & 1] + (size_t)b * PPOS * KQ;
    float acc = 0.0f;

#pragma unroll
    for (int dy = -1; dy <= 1; dy++) {
        int yy = py + dy;
        if (yy < 0 || yy > 31) continue;
#pragma unroll
        for (int dx = -1; dx <= 1; dx++) {
            int xx = px + dx;
            if (xx < 0 || xx > 31) continue;
            const __half* hr = hb + (size_t)(yy * 32 + xx) * KQ;
            int e = (dy + 1) * 3 + (dx + 1);
#pragma unroll
            for (int j = 0; j < 8; j++) {
                int cc = j * 64 + 2 * lane;
                __half2 d1 = *(const __half2*)(hr + cc);
                __half2 d2 = *(const __half2*)(hr + 512 + cc);
                float h0 = __half2float(d1.x) + __half2float(d2.x) * S3;
                float h1 = __half2float(d1.y) + __half2float(d2.y) * S3;
                acc += h0 * sWp[cc * 9 + e] + h1 * sWp[(cc + 1) * 9 + e];
            }
        }
    }

#pragma unroll
    for (int off = 16; off > 0; off >>= 1)
        acc += __shfl_xor_sync(0xFFFFFFFFu, acc, off);
    if (lane == 0)
        out[((size_t)b * TSTEPS + t) * PPOS + py * 32 + px] = acc + bpost[0];
}

// ---------------------------------------------------------------------------
extern "C" void kernel_launch(void* const* d_in, const int* in_sizes, int n_in,
                              void* d_out, int out_size)
{
    const float* x      = (const float*)d_in[0];
    const float* W_conv = (const float*)d_in[1];
    const float* b_conv = (const float*)d_in[2];
    const float* W_post = (const float*)d_in[3];
    const float* b_post = (const float*)d_in[4];
    float* out = (float*)d_out;

    static bool attr_set = false;
    if (!attr_set) {
        cudaFuncSetAttribute(fused_step_kernel,
                             cudaFuncAttributeMaxDynamicSharedMemorySize, SMEM_TOTAL);
        attr_set = true;
    }

    {
        size_t n = (size_t)BBATCH * PPOS * KQ / 2;     // = max(NH words, NC)
        init_state_kernel<<<(unsigned)((n + 255) / 256), 256>>>();
    }
    build_w16_kernel<<<(OO * CCH + 255) / 256, 256>>>(W_conv);

    dim3 fgrid(8, 36, BBATCH);   // y<32: gemm tiles (16ch each), y in [32,36): conv
    for (int t = 0; t < TSTEPS; t++) {
        fused_step_kernel<<<fgrid, 128, SMEM_TOTAL>>>(W_conv, b_conv, x,
                                                      W_post, b_post, out, t);
    }
    post_conv_kernel<<<2048, 256>>>(W_post, b_post, out, 31);
}

// round 17
// speedup vs baseline: 2.6320x; 1.9446x over previous
#include <cuda_runtime.h>
#include <cuda_fp16.h>
#include <cstdint>

// ---------------------------------------------------------------------------
// Problem constants
// ---------------------------------------------------------------------------
#define BBATCH 16
#define TSTEPS 32
#define CCH    512            // hidden channels
#define PPOS   1024           // 32*32 spatial positions
#define OO     2048           // 4 * CCH gate rows
#define KQ     512            // stored h width: single fp16 digit
#define NCHUNK 8              // 8 chunks of K=64 fp16 (w1*h1, f32 acc)
#define MP     128            // spatial positions per CTA (M)
#define NCHT   16             // channels per CTA

// ---------------------------------------------------------------------------
// Persistent state (ping-pong h across timesteps)
// ---------------------------------------------------------------------------
__device__ __align__(16) __half g_h16[2][(size_t)BBATCH * PPOS * KQ];  // 2 x 16.8 MB
__device__ __align__(16) float  g_cT[(size_t)BBATCH * PPOS * CCH];     // 33 MB
__device__ __align__(16) __half g_w16[(size_t)OO * 512];               // w1, 2.1 MB

// ---------------------------------------------------------------------------
// Helpers (compute_80-level PTX only)
// ---------------------------------------------------------------------------
__device__ __forceinline__ uint32_t smem_u32(const void* p) {
    uint32_t a;
    asm("{ .reg .u64 t; cvta.to.shared.u64 t, %1; cvt.u32.u64 %0, t; }"
        : "=r"(a) : "l"(p));
    return a;
}

#define SWZ128(o) ((o) ^ (((o) >> 3) & 0x70))

__device__ __forceinline__ void cp_async16(uint32_t dst, const void* src) {
    asm volatile("cp.async.cg.shared.global [%0], [%1], 16;" :: "r"(dst), "l"(src));
}
#define CP_COMMIT()   asm volatile("cp.async.commit_group;" ::: "memory")
#define CP_WAIT(n)    asm volatile("cp.async.wait_group %0;" :: "n"(n) : "memory")

__device__ __forceinline__ void ldsm_x4(uint32_t* r, uint32_t addr) {
    asm volatile("ldmatrix.sync.aligned.m8n8.x4.shared.b16 {%0,%1,%2,%3}, [%4];"
        : "=r"(r[0]), "=r"(r[1]), "=r"(r[2]), "=r"(r[3]) : "r"(addr));
}

// fp16 inputs, f32 accumulate
#define MMA_F32(d, a, b) \
    asm volatile( \
        "mma.sync.aligned.m16n8k16.row.col.f32.f16.f16.f32 " \
        "{%0,%1,%2,%3}, {%4,%5,%6,%7}, {%8,%9}, {%0,%1,%2,%3};" \
        : "+f"((d)[0]), "+f"((d)[1]), "+f"((d)[2]), "+f"((d)[3]) \
        : "r"((a)[0]), "r"((a)[1]), "r"((a)[2]), "r"((a)[3]), \
          "r"((b)[0]), "r"((b)[1]))

__device__ __forceinline__ float sigf(float v) { return 1.0f / (1.0f + __expf(-v)); }
__device__ __forceinline__ float tanh_f(float v) { return 2.0f * sigf(2.0f * v) - 1.0f; }

// ---------------------------------------------------------------------------
// Init kernels
// ---------------------------------------------------------------------------
__global__ void init_state_kernel() {
    const size_t NH = (size_t)BBATCH * PPOS * KQ / 2;     // buf0 as u32 words
    const size_t NC = (size_t)BBATCH * PPOS * CCH;
    size_t i = (size_t)blockIdx.x * 256 + threadIdx.x;
    if (i < NH) ((uint32_t*)g_h16[0])[i] = 0u;
    if (i < NC) g_cT[i] = 0.0f;
}

// w1 = fp16(W[:,1:513])
__global__ void build_w16_kernel(const float* __restrict__ W) {
    int i = blockIdx.x * 256 + threadIdx.x;
    if (i >= OO * CCH) return;
    int o = i >> 9, c = i & 511;
    g_w16[(size_t)o * 512 + c] = __float2half_rn(W[(size_t)o * 513 + 1 + c]);
}

// ---------------------------------------------------------------------------
// Fused kernel: fp16 gates-GEMM + LSTM for step t (blockIdx.y < 32) and,
// overlapped, the 3x3 post-conv for step t-1 (blockIdx.y in [32,36)). Both
// only READ h buffer [t&1]; the GEMM writes [(t+1)&1] -> no race.
//
// GEMM: 128 thr = 4 warps (2m x 2n), warp tile 64x32, CTA tile 128(p) x 64
// (n = 2 warps x [4 gates x 8 ch] interleaved, nt == gate). K = 512 fp16 in
// 8 chunks of 64; f32 accumulate. Register-resident LSTM epilogue.
// ---------------------------------------------------------------------------
#define STAGE_SZ   24576                  // A 16KB + B 8KB
#define SM_A(s)    ((s) * STAGE_SZ)
#define SM_B(s)    ((s) * STAGE_SZ + 16384)
#define SM_W0      73728                  // 64 floats
#define SM_BIAS    74240                  // 64 floats
#define SM_X       74752                  // 128 floats
#define SMEM_TOTAL (75264 + 1024)         // + align slack (~76 KB -> 2 CTAs/SM)

__global__ __launch_bounds__(128, 2) void fused_step_kernel(
    const float* __restrict__ W,      // [2048][513]
    const float* __restrict__ bconv,  // [2048]
    const float* __restrict__ x,      // [B][T][1024]
    const float* __restrict__ Wp,     // [512][3][3]
    const float* __restrict__ bpost,  // [1]
    float* __restrict__ out,          // [B][T][1024]
    int t)
{
    extern __shared__ char smem_raw[];
    const int tid = threadIdx.x;

    // =========================== CONV BRANCH ===============================
    if (blockIdx.y >= 32) {
        if (t == 0) return;
        float* sWp = (float*)smem_raw;
        for (int i = tid; i < 512 * 9; i += 128) sWp[i] = Wp[i];
        __syncthreads();

        const int b    = blockIdx.z;
        const int wid  = tid >> 5;
        const int lane = tid & 31;
        const int wg   = ((blockIdx.y - 32) * 8 + blockIdx.x) * 4 + wid;  // 0..127
        const __half* __restrict__ hb = g_h16[t & 1] + (size_t)b * PPOS * KQ;

#pragma unroll 1
        for (int pp = 0; pp < 8; pp++) {
            const int pix = wg * 8 + pp;
            const int py = pix >> 5, px = pix & 31;
            float acc = 0.0f;
#pragma unroll
            for (int dy = -1; dy <= 1; dy++) {
                int yy = py + dy;
                if (yy < 0 || yy > 31) continue;
#pragma unroll
                for (int dx = -1; dx <= 1; dx++) {
                    int xx = px + dx;
                    if (xx < 0 || xx > 31) continue;
                    const __half* hr = hb + (size_t)(yy * 32 + xx) * KQ;
                    int e = (dy + 1) * 3 + (dx + 1);
#pragma unroll
                    for (int j = 0; j < 8; j++) {
                        int cc = j * 64 + 2 * lane;
                        __half2 d1 = *(const __half2*)(hr + cc);
                        acc += __half2float(d1.x) * sWp[cc * 9 + e]
                             + __half2float(d1.y) * sWp[(cc + 1) * 9 + e];
                    }
                }
            }
#pragma unroll
            for (int off = 16; off > 0; off >>= 1)
                acc += __shfl_xor_sync(0xFFFFFFFFu, acc, off);
            if (lane == 0)
                out[((size_t)b * TSTEPS + (t - 1)) * PPOS + pix] = acc + bpost[0];
        }
        return;
    }

    // =========================== GEMM BRANCH ===============================
    const uint32_t sbase0 = smem_u32(smem_raw);
    const uint32_t abase  = (sbase0 + 1023) & ~1023u;
    char* smem = smem_raw + (abase - sbase0);

    const int wid  = tid >> 5;
    const int lane = tid & 31;
    const int mw   = wid >> 1;          // 0..1  (m warp)
    const int nw   = wid & 1;           // 0..1  (n warp: 8-ch group)

    const int b   = blockIdx.z;
    const int ch0 = blockIdx.y * NCHT;  // 16 channels per CTA
    const int p0  = blockIdx.x * MP;

    const __half* __restrict__ hb = g_h16[t & 1] + (size_t)b * PPOS * KQ;
    __half* __restrict__ hwr      = g_h16[(t + 1) & 1];

    // stage loader: chunk c -> stage s.  A: 1024 x 16B, B: 512 x 16B.
    // k-offset (c&7)*64 halfs for both A (h1) and B (w1).
    // B row r (0..63): o = gate*512 + ch0 + (r>>5)*8 + (r&7), gate = (r>>3)&3.
    auto load_stage = [&](int c, int s) {
        const int ka = (c & 7) * 64;
        const uint32_t da = abase + SM_A(s);
#pragma unroll
        for (int i = 0; i < 8; i++) {
            int idx = tid + i * 128;
            int r = idx >> 3, c8 = idx & 7;
            cp_async16(da + SWZ128(r * 128 + c8 * 16),
                       hb + (size_t)(p0 + r) * KQ + ka + c8 * 8);
        }
        const uint32_t db = abase + SM_B(s);
#pragma unroll
        for (int i = 0; i < 4; i++) {
            int idx = tid + i * 128;
            int r = idx >> 3, c8 = idx & 7;
            int o = (((r >> 3) & 3) * 512) + ch0 + ((r >> 5) * 8) + (r & 7);
            cp_async16(db + SWZ128(r * 128 + c8 * 16),
                       g_w16 + (size_t)o * 512 + ka + c8 * 8);
        }
        CP_COMMIT();
    };

    load_stage(0, 0);
    load_stage(1, 1);
    {
        float* sW0   = (float*)(smem + SM_W0);
        float* sBias = (float*)(smem + SM_BIAS);
        float* sX    = (float*)(smem + SM_X);
        if (tid < 64) {                            // idx = g*16 + c16
            int o = (tid >> 4) * 512 + ch0 + (tid & 15);
            sW0[tid]   = W[(size_t)o * 513];
            sBias[tid] = bconv[o];
        }
        sX[tid] = x[((size_t)b * TSTEPS + t) * PPOS + p0 + tid];
    }

    float acc1[4][4][4];                           // f32 acc (64 regs)
#pragma unroll
    for (int mt = 0; mt < 4; mt++)
#pragma unroll
        for (int nt = 0; nt < 4; nt++)
#pragma unroll
            for (int e = 0; e < 4; e++) acc1[mt][nt][e] = 0.0f;

    // Base swizzled ldmatrix addresses (kk=0); +16-row steps (+2048B) keep the
    // SW128 mask; kk steps are pure XOR with kk*32 (mask depends on row&7 only).
    const uint32_t rA0 = SWZ128((uint32_t)(mw * 64 + (lane & 15)) * 128
                                + (uint32_t)(lane >> 4) * 16);
    const uint32_t rB0 = SWZ128((uint32_t)((lane & 7) + ((lane >> 4) << 3)) * 128
                                + (uint32_t)((lane >> 3) & 1) * 16);
    const uint32_t nwofs = (uint32_t)nw * 32 * 128;   // n-warp row offset (mask-safe)

#pragma unroll 1
    for (int c = 0; c < NCHUNK; c++) {
        const int s = c % 3;
        if (c + 2 < NCHUNK) CP_WAIT(1); else CP_WAIT(0);
        __syncthreads();                           // chunk c ready; stage (c+2)%3 free
        if (c + 2 < NCHUNK) load_stage(c + 2, (c + 2) % 3);

        const uint32_t Ab = abase + SM_A(s);
        const uint32_t Bb = abase + SM_B(s);
#pragma unroll
        for (int kk = 0; kk < 4; kk++) {
            uint32_t af[4][4], bf[2][4];
#pragma unroll
            for (int mt = 0; mt < 4; mt++)
                ldsm_x4(af[mt], Ab + ((rA0 + mt * 2048) ^ (kk * 32)));
#pragma unroll
            for (int np = 0; np < 2; np++)
                ldsm_x4(bf[np], Bb + nwofs + ((rB0 + np * 2048) ^ (kk * 32)));
#pragma unroll
            for (int mt = 0; mt < 4; mt++)
#pragma unroll
                for (int nt = 0; nt < 4; nt++)
                    MMA_F32(acc1[mt][nt], af[mt], &bf[nt >> 1][(nt & 1) * 2]);
        }
    }

    // ---- register-resident LSTM epilogue ----
    float* sW0   = (float*)(smem + SM_W0);
    float* sBias = (float*)(smem + SM_BIAS);
    float* sX    = (float*)(smem + SM_X);

#pragma unroll
    for (int mt = 0; mt < 4; mt++) {
#pragma unroll
        for (int half = 0; half < 2; half++) {
            const int m = mw * 64 + mt * 16 + (lane >> 2) + half * 8;
            const int p = p0 + m;
            const float xv = sX[m];
            float* __restrict__ cb = g_cT + ((size_t)b * PPOS + p) * CCH;
            __half* __restrict__ hr = hwr + ((size_t)b * PPOS + p) * KQ;
            const int chb = ch0 + nw * 8 + (lane & 3) * 2;
            float2 cold = *(float2*)(cb + chb);
            float cn[2];
            __half2 d1o;
#pragma unroll
            for (int e = 0; e < 2; e++) {
                const int idx = half * 2 + e;
                const int cfs = nw * 8 + (lane & 3) * 2 + e;   // 0..15
                float g4[4];
#pragma unroll
                for (int g = 0; g < 4; g++) {
                    g4[g] = acc1[mt][g][idx]
                          + sW0[g * 16 + cfs] * xv + sBias[g * 16 + cfs];
                }
                float cold_e = (e == 0) ? cold.x : cold.y;
                cn[e] = sigf(g4[1]) * cold_e + sigf(g4[0]) + tanh_f(g4[3]);
                float hv = sigf(g4[2]) + tanh_f(cn[e]);
                __half h1 = __float2half_rn(hv);
                if (e == 0) d1o.x = h1; else d1o.y = h1;
            }
            *(float2*)(cb + chb) = make_float2(cn[0], cn[1]);
            *(__half2*)(hr + chb) = d1o;
        }
    }
}

// ---------------------------------------------------------------------------
// Standalone post-conv (only for the final step t=31), fp16 h.
// ---------------------------------------------------------------------------
__global__ __launch_bounds__(256) void post_conv_kernel(
    const float* __restrict__ Wp,
    const float* __restrict__ bpost,
    float* __restrict__ out,
    int t)
{
    __shared__ float sWp[512 * 9];
    for (int i = threadIdx.x; i < 512 * 9; i += 256) sWp[i] = Wp[i];
    __syncthreads();

    int warp = (blockIdx.x * 256 + threadIdx.x) >> 5;
    int lane = threadIdx.x & 31;
    int b  = warp >> 10;
    int py = (warp >> 5) & 31;
    int px = warp & 31;

    const __half* __restrict__ hb = g_h16[(t + 1) & 1] + (size_t)b * PPOS * KQ;
    float acc = 0.0f;

#pragma unroll
    for (int dy = -1; dy <= 1; dy++) {
        int yy = py + dy;
        if (yy < 0 || yy > 31) continue;
#pragma unroll
        for (int dx = -1; dx <= 1; dx++) {
            int xx = px + dx;
            if (xx < 0 || xx > 31) continue;
            const __half* hr = hb + (size_t)(yy * 32 + xx) * KQ;
            int e = (dy + 1) * 3 + (dx + 1);
#pragma unroll
            for (int j = 0; j < 8; j++) {
                int cc = j * 64 + 2 * lane;
                __half2 d1 = *(const __half2*)(hr + cc);
                acc += __half2float(d1.x) * sWp[cc * 9 + e]
                     + __half2float(d1.y) * sWp[(cc + 1) * 9 + e];
            }
        }
    }

#pragma unroll
    for (int off = 16; off > 0; off >>= 1)
        acc += __shfl_xor_sync(0xFFFFFFFFu, acc, off);
    if (lane == 0)
        out[((size_t)b * TSTEPS + t) * PPOS + py * 32 + px] = acc + bpost[0];
}

// ---------------------------------------------------------------------------
extern "C" void kernel_launch(void* const* d_in, const int* in_sizes, int n_in,
                              void* d_out, int out_size)
{
    const float* x      = (const float*)d_in[0];
    const float* W_conv = (const float*)d_in[1];
    const float* b_conv = (const float*)d_in[2];
    const float* W_post = (const float*)d_in[3];
    const float* b_post = (const float*)d_in[4];
    float* out = (float*)d_out;

    static bool attr_set = false;
    if (!attr_set) {
        cudaFuncSetAttribute(fused_step_kernel,
                             cudaFuncAttributeMaxDynamicSharedMemorySize, SMEM_TOTAL);
        attr_set = true;
    }

    {
        size_t n = (size_t)BBATCH * PPOS * CCH;        // >= all word counts
        init_state_kernel<<<(unsigned)((n + 255) / 256), 256>>>();
    }
    build_w16_kernel<<<(OO * CCH + 255) / 256, 256>>>(W_conv);

    dim3 fgrid(8, 36, BBATCH);   // y<32: gemm tiles (16ch each), y in [32,36): conv
    for (int t = 0; t < TSTEPS; t++) {
        fused_step_kernel<<<fgrid, 128, SMEM_TOTAL>>>(W_conv, b_conv, x,
                                                      W_post, b_post, out, t);
    }
    post_conv_kernel<<<2048, 256>>>(W_post, b_post, out, 31);
}